// round 3
// baseline (speedup 1.0000x reference)
#include <cuda_runtime.h>
#include <cstdint>

// Problem constants (from reference_code)
constexpr int F     = 8;
constexpr int B     = 4096;
constexpr int L     = 20;
constexpr int BL    = B * L;        // 81920
constexpr int VOCAB = 1000000;
constexpr int DIM   = 128;          // 128 floats = 32 float4 per row
constexpr int ROWS  = F * BL;       // 655360 output rows
constexpr int R     = 8;            // rows per warp
constexpr int WARPS = 8;            // warps per block
constexpr int RPB   = R * WARPS;    // 64 rows per block (64 | BL)

// perm for SPLIT_SIZES=(4,4), SPLIT_ORDER=(1,0): [4,5,6,7,0,1,2,3] == (f+4)&7

__global__ __launch_bounds__(WARPS * 32)
void emb_gather_kernel(const int* __restrict__ vals,
                       const float4* __restrict__ table,
                       float4* __restrict__ out)
{
    __shared__ unsigned s_slot[RPB];

    const int tid  = threadIdx.x;
    const int warp = tid >> 5;
    const int lane = tid & 31;

    const int block_base = blockIdx.x * RPB;       // first output row of block

    // Stage ids for the whole block: one coalesced 256B load, slots to smem.
    if (tid < RPB) {
        const int row   = block_base + tid;
        const int f     = row / BL;                // same feature for whole block
        const int pos   = row - f * BL;
        const int src_f = (f + 4) & 7;             // feature-block permutation
        const unsigned id = (unsigned)__ldg(&vals[src_f * BL + pos]);
        s_slot[tid] = id % (unsigned)VOCAB;
    }
    __syncthreads();

    // Each warp: 8 independent 512B row gathers in flight.
    const int wbase = warp * R;
    unsigned slot[R];
    #pragma unroll
    for (int r = 0; r < R; r++)
        slot[r] = s_slot[wbase + r];

    float4 v[R];
    #pragma unroll
    for (int r = 0; r < R; r++)
        v[r] = __ldg(&table[(size_t)slot[r] * (DIM / 4) + lane]);

    // streaming stores: evict-first, keep L2 for table rows
    const size_t obase = (size_t)(block_base + wbase) * (DIM / 4) + lane;
    #pragma unroll
    for (int r = 0; r < R; r++)
        __stcs(&out[obase + (size_t)r * (DIM / 4)], v[r]);
}

extern "C" void kernel_launch(void* const* d_in, const int* in_sizes, int n_in,
                              void* d_out, int out_size)
{
    const int*    vals  = (const int*)d_in[0];     // [F, B*L] int32
    const float4* table = (const float4*)d_in[1];  // [VOCAB, DIM] float32
    float4*       out   = (float4*)d_out;          // [F, B*L, DIM] float32

    const int blocks = ROWS / RPB;                 // 10240
    emb_gather_kernel<<<blocks, WARPS * 32>>>(vals, table, out);
}